// round 5
// baseline (speedup 1.0000x reference)
#include <cuda_runtime.h>

#define NQ 6
#define NL 3

typedef unsigned long long ull;

// Weight-only part of each gate: M = RZ(w2) @ RY(w1) @ RZ(w0), complex 2x2.
__device__ float2 g_M[NL * NQ * 4];

__global__ void setup_gates(const float* __restrict__ w) {
    int g = threadIdx.x;
    if (g >= NL * NQ) return;
    float w0 = w[g * 3 + 0];
    float w1 = w[g * 3 + 1];
    float w2 = w[g * 3 + 2];
    float s1, c1, sp_, cp_, sm2, cm2;
    sincosf(0.5f * w1, &s1, &c1);
    sincosf(0.5f * (w0 + w2), &sp_, &cp_);
    sincosf(0.5f * (w0 - w2), &sm2, &cm2);
    g_M[g * 4 + 0] = make_float2(c1 * cp_, -c1 * sp_);   // M00
    g_M[g * 4 + 1] = make_float2(-s1 * cm2, -s1 * sm2);  // M01
    g_M[g * 4 + 2] = make_float2(s1 * cm2, -s1 * sm2);   // M10
    g_M[g * 4 + 3] = make_float2(c1 * cp_, c1 * sp_);    // M11
}

// ---- packed f32x2 helpers ----
__device__ __forceinline__ ull fma2(ull a, ull b, ull c) {
    ull d; asm("fma.rn.f32x2 %0,%1,%2,%3;" : "=l"(d) : "l"(a), "l"(b), "l"(c)); return d;
}
__device__ __forceinline__ ull mul2(ull a, ull b) {
    ull d; asm("mul.rn.f32x2 %0,%1,%2;" : "=l"(d) : "l"(a), "l"(b)); return d;
}
__device__ __forceinline__ ull pk(float lo, float hi) {
    ull d; asm("mov.b64 %0,{%1,%2};" : "=l"(d) : "f"(lo), "f"(hi)); return d;
}
__device__ __forceinline__ ull sp2(float x) { return pk(x, x); }
__device__ __forceinline__ float flo(ull v) { return __uint_as_float((unsigned)v); }
__device__ __forceinline__ float fhi(ull v) { return __uint_as_float((unsigned)(v >> 32)); }
__device__ __forceinline__ ull lsw(ull v) { return pk(fhi(v), flo(v)); }  // lane swap
__device__ __forceinline__ float tanh_fast(float x) {
    float y; asm("tanh.approx.f32 %0, %1;" : "=f"(y) : "f"(x)); return y;
}

// Gate on local wire w in {1..4}: pack-index stride S = 1<<(4-w). Element-wise packed.
// Coefficients derived inline from (c, s) and the layer's M to keep live ranges short.
template <int S>
__device__ __forceinline__ void gate_local(ull* RE, ull* IM, const float2* m,
                                           float c, float s) {
    float2 m00 = m[0], m01 = m[1], m10 = m[2], m11 = m[3];
    float g00x = fmaf(c, m00.x, s * m01.x),  g00y = fmaf(c, m00.y, s * m01.y);
    float g01x = fmaf(-s, m00.x, c * m01.x), g01y = fmaf(-s, m00.y, c * m01.y);
    float g10x = fmaf(c, m10.x, s * m11.x),  g10y = fmaf(c, m10.y, s * m11.y);
    float g11x = fmaf(-s, m10.x, c * m11.x), g11y = fmaf(-s, m10.y, c * m11.y);
    ull x00 = sp2(g00x), ny00 = sp2(-g00y), y00 = sp2(g00y);
    ull x01 = sp2(g01x), ny01 = sp2(-g01y), y01 = sp2(g01y);
    ull x10 = sp2(g10x), ny10 = sp2(-g10y), y10 = sp2(g10y);
    ull x11 = sp2(g11x), ny11 = sp2(-g11y), y11 = sp2(g11y);
#pragma unroll
    for (int t = 0; t < 8; t++) {
        int K0 = ((t & ~(S - 1)) << 1) | (t & (S - 1));
        int K1 = K0 + S;
        ull r0 = RE[K0], i0 = IM[K0], r1 = RE[K1], i1 = IM[K1];
        RE[K0] = fma2(x00, r0, fma2(ny00, i0, fma2(x01, r1, mul2(ny01, i1))));
        IM[K0] = fma2(x00, i0, fma2(y00, r0, fma2(x01, i1, mul2(y01, r1))));
        RE[K1] = fma2(x10, r0, fma2(ny10, i0, fma2(x11, r1, mul2(ny11, i1))));
        IM[K1] = fma2(x10, i0, fma2(y10, r0, fma2(x11, i1, mul2(y11, r1))));
    }
}

// Gate on wire 5 (the two lanes inside each pack), swap-form:
// out = P .* st + Q .* laneswap(st), P=(G00,G11), Q=(G01,G10).
__device__ __forceinline__ void gate_w5(ull* RE, ull* IM, const float2* m,
                                        float c, float s) {
    float2 m00 = m[0], m01 = m[1], m10 = m[2], m11 = m[3];
    float g00x = fmaf(c, m00.x, s * m01.x),  g00y = fmaf(c, m00.y, s * m01.y);
    float g01x = fmaf(-s, m00.x, c * m01.x), g01y = fmaf(-s, m00.y, c * m01.y);
    float g10x = fmaf(c, m10.x, s * m11.x),  g10y = fmaf(c, m10.y, s * m11.y);
    float g11x = fmaf(-s, m10.x, c * m11.x), g11y = fmaf(-s, m10.y, c * m11.y);
    ull Px = pk(g00x, g11x), Py = pk(g00y, g11y), nPy = pk(-g00y, -g11y);
    ull Qx = pk(g01x, g10x), Qy = pk(g01y, g10y), nQy = pk(-g01y, -g10y);
#pragma unroll
    for (int K = 0; K < 16; K++) {
        ull r = RE[K], i = IM[K];
        ull rs = lsw(r), is = lsw(i);
        RE[K] = fma2(Px, r, fma2(nPy, i, fma2(Qx, rs, mul2(nQy, is))));
        IM[K] = fma2(Px, i, fma2(Py, r, fma2(Qx, is, mul2(Qy, rs))));
    }
}

// Gate on wire 0 fused with a PENDING cnot(5,0) from the preceding ring.
// The cnot(5,0) lane merge is absorbed into asymmetric coefficient packs:
//   out = pk(Gd,Go) .* mine + pk(Go,Gd) .* partner     (no lane merges needed)
__device__ __forceinline__ void gate_w0_fused(ull* RE, ull* IM, float2 Gd, float2 Go) {
    ull dx = pk(Gd.x, Go.x), ox = pk(Go.x, Gd.x);
    ull dy = pk(Gd.y, Go.y), oy = pk(Go.y, Gd.y);
    ull ndy = pk(-Gd.y, -Go.y), noy = pk(-Go.y, -Gd.y);
#pragma unroll
    for (int K = 0; K < 16; K++) {
        ull pr = __shfl_xor_sync(0xffffffffu, RE[K], 1);
        ull pi = __shfl_xor_sync(0xffffffffu, IM[K], 1);
        ull r = RE[K], i = IM[K];
        RE[K] = fma2(dx, r, fma2(ndy, i, fma2(ox, pr, mul2(noy, pi))));
        IM[K] = fma2(dx, i, fma2(dy, r, fma2(ox, pi, mul2(oy, pr))));
    }
}

__device__ __forceinline__ void swp(ull& a, ull& b) { ull t = a; a = b; b = t; }

// CNOT ring WITHOUT the final cnot(5,0): (0,1)(1,2)(2,3)(3,4)(4,5).
// The trailing cnot(5,0) is fused into the next wire-0 gate (or readout).
__device__ __forceinline__ void cnot_ring_partial(ull* RE, ull* IM, int p) {
    // cnot(0,1): p==1 threads flip pack bit3
    {
        bool pb = (p != 0);
#pragma unroll
        for (int K = 0; K < 8; K++) {
            ull a = RE[K], b = RE[K + 8];
            RE[K] = pb ? b : a; RE[K + 8] = pb ? a : b;
            ull c = IM[K], d = IM[K + 8];
            IM[K] = pb ? d : c; IM[K + 8] = pb ? c : d;
        }
    }
    // cnot(1,2): bit3==1 -> flip bit2  (free renames)
    swp(RE[8], RE[12]); swp(IM[8], IM[12]);
    swp(RE[9], RE[13]); swp(IM[9], IM[13]);
    swp(RE[10], RE[14]); swp(IM[10], IM[14]);
    swp(RE[11], RE[15]); swp(IM[11], IM[15]);
    // cnot(2,3): bit2==1 -> flip bit1
    swp(RE[4], RE[6]);  swp(IM[4], IM[6]);
    swp(RE[5], RE[7]);  swp(IM[5], IM[7]);
    swp(RE[12], RE[14]); swp(IM[12], IM[14]);
    swp(RE[13], RE[15]); swp(IM[13], IM[15]);
    // cnot(3,4): bit1==1 -> flip bit0
    swp(RE[2], RE[3]);  swp(IM[2], IM[3]);
    swp(RE[6], RE[7]);  swp(IM[6], IM[7]);
    swp(RE[10], RE[11]); swp(IM[10], IM[11]);
    swp(RE[14], RE[15]); swp(IM[14], IM[15]);
    // cnot(4,5): bit0==1 -> swap the two lanes of the pack
#pragma unroll
    for (int K = 1; K < 16; K += 2) {
        RE[K] = lsw(RE[K]);
        IM[K] = lsw(IM[K]);
    }
}

__global__ __launch_bounds__(128, 5)
void qsim_kernel(const float* __restrict__ x, float* __restrict__ out, int B) {
    __shared__ float2 sM[NL * NQ * 4];
    if (threadIdx.x < NL * NQ * 4) sM[threadIdx.x] = g_M[threadIdx.x];
    __syncthreads();

    int tid = blockIdx.x * blockDim.x + threadIdx.x;
    int b = tid >> 1;
    if (b >= B) return;
    int p = tid & 1;  // this thread's wire-0 (MSB) value

    // Pre-scaled half-angles only (6 regs); sincos recomputed per use (MUFU is idle).
    float th[NQ];
#pragma unroll
    for (int q = 0; q < NQ; q++) {
        th[q] = 1.5707963267948966f * tanh_fast(x[b * NQ + q]);
    }

    // 32 local amps packed: RE[K] = (re_{2K}, re_{2K+1}), pack lane = wire5.
    // Pack-index bits 3..0 = wires 1..4.
    ull RE[16], IM[16];

    // ---- Layer 0: product state |0..0> -> tensor of first gate columns ----
    {
        float cq, sq;
        float2 a;  // wire-0 factor for this thread
        {
            __sincosf(th[0], &sq, &cq);
            float2 ma = p ? sM[2] : sM[0];
            float2 mb = p ? sM[3] : sM[1];
            a.x = fmaf(cq, ma.x, sq * mb.x);
            a.y = fmaf(cq, ma.y, sq * mb.y);
        }
        {
            __sincosf(th[5], &sq, &cq);
            float2 m00 = sM[5 * 4 + 0], m01 = sM[5 * 4 + 1];
            float2 m10 = sM[5 * 4 + 2], m11 = sM[5 * 4 + 3];
            float2 v0 = make_float2(fmaf(cq, m00.x, sq * m01.x),
                                    fmaf(cq, m00.y, sq * m01.y));
            float2 v1 = make_float2(fmaf(cq, m10.x, sq * m11.x),
                                    fmaf(cq, m10.y, sq * m11.y));
            ull V5X = pk(v0.x, v1.x), V5Y = pk(v0.y, v1.y), V5Yn = pk(-v0.y, -v1.y);
            RE[0] = fma2(sp2(a.x), V5X, mul2(sp2(a.y), V5Yn));
            IM[0] = fma2(sp2(a.x), V5Y, mul2(sp2(a.y), V5X));
        }
#pragma unroll
        for (int q = 1; q <= 4; q++) {
            __sincosf(th[q], &sq, &cq);
            float2 m00 = sM[q * 4 + 0], m01 = sM[q * 4 + 1];
            float2 m10 = sM[q * 4 + 2], m11 = sM[q * 4 + 3];
            float2 v0 = make_float2(fmaf(cq, m00.x, sq * m01.x),
                                    fmaf(cq, m00.y, sq * m01.y));
            float2 v1 = make_float2(fmaf(cq, m10.x, sq * m11.x),
                                    fmaf(cq, m10.y, sq * m11.y));
            ull x0 = sp2(v0.x), ny0 = sp2(-v0.y), y0 = sp2(v0.y);
            ull x1 = sp2(v1.x), ny1 = sp2(-v1.y), y1 = sp2(v1.y);
            int n = 1 << (q - 1);
#pragma unroll
            for (int k = 15; k >= 0; k--) {
                if (k < n) {
                    ull r = RE[k], i = IM[k];
                    RE[2 * k + 1] = fma2(x1, r, mul2(ny1, i));
                    IM[2 * k + 1] = fma2(x1, i, mul2(y1, r));
                    RE[2 * k]     = fma2(x0, r, mul2(ny0, i));
                    IM[2 * k]     = fma2(x0, i, mul2(y0, r));
                }
            }
        }
    }
    cnot_ring_partial(RE, IM, p);  // cnot(5,0) pending -> fused into next gate_w0

    // ---- Layers 1..2 ----
#pragma unroll
    for (int layer = 1; layer < NL; layer++) {
        const float2* mbase = &sM[layer * NQ * 4];
        float cq, sq;
        // wire 0 (cross-thread), fused with pending cnot(5,0).
        // Only row p of G is needed: from row entries a=m[2p], b=m[2p+1]:
        //   u = c*a + s*b, v = -s*a + c*b; Gd = p?v:u, Go = p?u:v.
        {
            __sincosf(th[0], &sq, &cq);
            float2 ma = p ? mbase[2] : mbase[0];
            float2 mb = p ? mbase[3] : mbase[1];
            float2 u = make_float2(fmaf(cq, ma.x, sq * mb.x), fmaf(cq, ma.y, sq * mb.y));
            float2 v = make_float2(fmaf(-sq, ma.x, cq * mb.x), fmaf(-sq, ma.y, cq * mb.y));
            float2 Gd = p ? v : u;
            float2 Go = p ? u : v;
            gate_w0_fused(RE, IM, Gd, Go);
        }
        // wires 1..4 (local packed)
        __sincosf(th[1], &sq, &cq);
        gate_local<8>(RE, IM, mbase + 4, cq, sq);
        __sincosf(th[2], &sq, &cq);
        gate_local<4>(RE, IM, mbase + 8, cq, sq);
        __sincosf(th[3], &sq, &cq);
        gate_local<2>(RE, IM, mbase + 12, cq, sq);
        __sincosf(th[4], &sq, &cq);
        gate_local<1>(RE, IM, mbase + 16, cq, sq);
        // wire 5 (intra-pack, swap-form)
        __sincosf(th[5], &sq, &cq);
        gate_w5(RE, IM, mbase + 20, cq, sq);

        cnot_ring_partial(RE, IM, p);  // cnot(5,0) pending again
    }

    // ---- Readout (final cnot(5,0) folded into the e0 sign), packed accumulation ----
    const ull ONE = sp2(1.0f), MONE = sp2(-1.0f);
    ull At = sp2(0.0f), A1 = At, A2 = At, A3 = At, A4 = At;
#pragma unroll
    for (int K = 0; K < 16; K++) {
        ull PR = fma2(RE[K], RE[K], mul2(IM[K], IM[K]));
        At = fma2(ONE, PR, At);
        A1 = fma2((K & 8) ? MONE : ONE, PR, A1);
        A2 = fma2((K & 4) ? MONE : ONE, PR, A2);
        A3 = fma2((K & 2) ? MONE : ONE, PR, A3);
        A4 = fma2((K & 1) ? MONE : ONE, PR, A4);
    }
    float dsum = flo(At) - fhi(At);
    float e0 = p ? -dsum : dsum;  // lo lane: wire0 = p; hi lane: wire0 = 1-p
    float e5 = dsum;              // wire5 = lane, unaffected by cnot(5,0)
    float e1 = flo(A1) + fhi(A1);
    float e2 = flo(A2) + fhi(A2);
    float e3 = flo(A3) + fhi(A3);
    float e4 = flo(A4) + fhi(A4);
    e0 += __shfl_xor_sync(0xffffffffu, e0, 1);
    e1 += __shfl_xor_sync(0xffffffffu, e1, 1);
    e2 += __shfl_xor_sync(0xffffffffu, e2, 1);
    e3 += __shfl_xor_sync(0xffffffffu, e3, 1);
    e4 += __shfl_xor_sync(0xffffffffu, e4, 1);
    e5 += __shfl_xor_sync(0xffffffffu, e5, 1);

    float* ob = out + (size_t)b * NQ;
    if (p == 0) {
        ob[0] = e0; ob[1] = e1; ob[2] = e2;
    } else {
        ob[3] = e3; ob[4] = e4; ob[5] = e5;
    }
}

extern "C" void kernel_launch(void* const* d_in, const int* in_sizes, int n_in,
                              void* d_out, int out_size) {
    const float* x = (const float*)d_in[0];
    const float* w = (const float*)d_in[1];
    float* out = (float*)d_out;
    int B = in_sizes[0] / NQ;

    setup_gates<<<1, 32>>>(w);

    const int threads = 128;
    long long total = 2LL * B;
    int blocks = (int)((total + threads - 1) / threads);
    qsim_kernel<<<blocks, threads>>>(x, out, B);
}